// round 13
// baseline (speedup 1.0000x reference)
#include <cuda_runtime.h>
#include <cstdint>

// Problem dims
#define TT 128
#define BB 256
#define II 512
#define HH 1024
#define VV 128
#define OO 64
#define NG 4096   // 4*H

// Decomposition
#define NCTA 128        // 2 batch-blocks x 64 unit-blocks
#define BT 128          // batch rows per CTA (M)
#define UT 16           // hidden units per CTA
#define CT 64           // gate cols per CTA (N)
#define KC 64           // K chunk
#define NKC (HH/KC)     // 16
#define NTHR 512        // 16 warps: 8x2 grid, 16x32 tile per warp

#define AS_STRIDE 68
#define STAGE_FLOATS ((BT + CT) * AS_STRIDE)   // 13056

#define PS 65           // P table row stride

// smem float offsets
#define OFF_P   0                         // 128*65 = 8320 floats
#define OFF_TOK 8320                      // 136 ints
#define OFF_B0  8456
#define OFF_B1  (OFF_B0 + STAGE_FLOATS)   // 21512
#define OFF_B2  (OFF_B1 + STAGE_FLOATS)   // 34568
#define SMEM_FLOATS (OFF_B2 + STAGE_FLOATS)   // 190496 B

// ---- static scratch ----
__device__ float g_h[2*BB*HH];        // ping-pong hidden state (tf32; fp32 last step)
__device__ float g_w[NG*HH];          // tf32-pre-rounded w_hh
__device__ unsigned g_cnt;
__device__ unsigned g_rel;

__device__ __forceinline__ float tf32r(float x) {
    unsigned v; asm("cvt.rna.tf32.f32 %0, %1;" : "=r"(v) : "f"(x));
    return __uint_as_float(v);
}
__device__ __forceinline__ unsigned ld_acq(const unsigned* p) {
    unsigned v; asm volatile("ld.acquire.gpu.u32 %0, [%1];" : "=r"(v) : "l"(p) : "memory");
    return v;
}
__device__ __forceinline__ void grid_sync() {
    __syncthreads();
    if (threadIdx.x == 0) {
        unsigned r0 = ld_acq(&g_rel);
        __threadfence();
        unsigned old = atomicAdd(&g_cnt, 1u);
        if (old == (unsigned)(NCTA - 1)) {
            g_cnt = 0; __threadfence(); atomicAdd(&g_rel, 1u);
        } else {
            while (ld_acq(&g_rel) == r0) { }
        }
    }
    __syncthreads();
}

// col j -> gate=(j>>3)&3, unit=(j>>5)*8+(j&7): all 4 gates of a cell in one thread.
__device__ __forceinline__ int colIdx(int j, int unit0) {
    return (((j >> 3) & 3) << 10) + unit0 + ((j >> 5) << 3) + (j & 7);
}

__device__ __forceinline__ void mma8(float d[4], const unsigned a[4],
                                     unsigned b0, unsigned b1) {
    asm volatile(
        "mma.sync.aligned.m16n8k8.row.col.f32.tf32.tf32.f32 "
        "{%0,%1,%2,%3}, {%4,%5,%6,%7}, {%8,%9}, {%0,%1,%2,%3};\n"
        : "+f"(d[0]), "+f"(d[1]), "+f"(d[2]), "+f"(d[3])
        : "r"(a[0]), "r"(a[1]), "r"(a[2]), "r"(a[3]), "r"(b0), "r"(b1));
}
__device__ __forceinline__ void ldsm4(unsigned addr, unsigned& r0, unsigned& r1,
                                      unsigned& r2, unsigned& r3) {
    asm volatile("ldmatrix.sync.aligned.m8n8.x4.shared.b16 {%0,%1,%2,%3}, [%4];"
                 : "=r"(r0), "=r"(r1), "=r"(r2), "=r"(r3) : "r"(addr));
}
__device__ __forceinline__ void cpa16(unsigned dst, const float* src) {
    asm volatile("cp.async.cg.shared.global [%0], [%1], 16;" :: "r"(dst), "l"(src));
}
#define CP_COMMIT() asm volatile("cp.async.commit_group;" ::: "memory")
template<int N> __device__ __forceinline__ void cp_wait() {
    asm volatile("cp.async.wait_group %0;" :: "n"(N) : "memory");
}

// fast pointwise ops
__device__ __forceinline__ float fsig(float x) {
    return __fdividef(1.0f, 1.0f + __expf(-x));
}
__device__ __forceinline__ float ftanh(float x) {
    return 1.0f - 2.0f * __fdividef(1.0f, __expf(2.0f * x) + 1.0f);
}

// Synchronous tile load with tf32 rounding (P-table phase only).
__device__ __forceinline__ void load_tiles_cvt(
    float* As, float* Ws,
    const float* __restrict__ A, int lda,
    const float* __restrict__ W, int ldw,
    int kc, int unit0, int tid)
{
#pragma unroll
    for (int i = 0; i < 4; i++) {               // A: 2048 float4 / 512 thr
        int id = tid + NTHR * i;
        int r = id >> 4, q = id & 15;
        float4 v = __ldcg((const float4*)(A + (size_t)r * lda + kc + q * 4));
        v.x = tf32r(v.x); v.y = tf32r(v.y); v.z = tf32r(v.z); v.w = tf32r(v.w);
        *(float4*)(As + r * AS_STRIDE + q * 4) = v;
    }
#pragma unroll
    for (int i = 0; i < 2; i++) {               // W: 1024 float4 / 512 thr
        int id = tid + NTHR * i;
        int r = id >> 4, q = id & 15;
        float4 v = __ldcg((const float4*)(W + (size_t)colIdx(r, unit0) * ldw + kc + q * 4));
        v.x = tf32r(v.x); v.y = tf32r(v.y); v.z = tf32r(v.z); v.w = tf32r(v.w);
        *(float4*)(Ws + r * AS_STRIDE + q * 4) = v;
    }
}

// ldmatrix-based chunk MMA for 8x2 grid: 1 A fragment (16 rows), 2 B x4 fragments.
__device__ __forceinline__ void mma_chunk(
    unsigned stg, unsigned a_lm, const unsigned b_lm[2],
    float acc[4][4])
{
#pragma unroll
    for (int kk = 0; kk < KC; kk += 8) {
        unsigned a[4], b[2][4];
        ldsm4(stg + a_lm + kk * 4, a[0], a[1], a[2], a[3]);
        ldsm4(stg + b_lm[0] + kk * 4, b[0][0], b[0][1], b[0][2], b[0][3]);
        ldsm4(stg + b_lm[1] + kk * 4, b[1][0], b[1][1], b[1][2], b[1][3]);
        mma8(acc[0], a, b[0][0], b[0][1]);
        mma8(acc[1], a, b[0][2], b[0][3]);
        mma8(acc[2], a, b[1][0], b[1][1]);
        mma8(acc[3], a, b[1][2], b[1][3]);
    }
}

__global__ void __launch_bounds__(NTHR, 1)
lstm_persistent_kernel(
    const void* __restrict__ inp_raw,
    const float* __restrict__ h0,
    const float* __restrict__ c0,
    const float* __restrict__ emb,
    const float* __restrict__ w_ih,
    const float* __restrict__ w_hh,
    const float* __restrict__ b_ih,
    const float* __restrict__ b_hh,
    const float* __restrict__ w_out,
    const float* __restrict__ b_out,
    float* __restrict__ out)
{
    extern __shared__ float sm[];
    float* Psm   = sm + OFF_P;
    int*   toksm = (int*)(sm + OFF_TOK);

    const int tid  = threadIdx.x;
    const int lane = tid & 31, wid = tid >> 5;
    const int warp_m = wid >> 1, warp_n = wid & 1;  // 8x2
    const int cid = blockIdx.x;
    const int bi = cid >> 6, hi = cid & 63;
    const int b0 = bi * BT;
    const int unit0 = hi * UT;
    const int lg = lane >> 2, lt = lane & 3;

    const unsigned sbase = (unsigned)__cvta_generic_to_shared(sm);
    const int* inp32 = (const int*)inp_raw;
    const long long* inp64 = (const long long*)inp_raw;

    // ---- token dtype detection ----
    if (tid == 0) toksm[128] = 0;
    __syncthreads();
    {
        int f = 0;
        for (int i = tid; i < 128; i += NTHR)
            if (inp32[2 * i + 1] != 0) f = 1;
        if (f) atomicOr(&toksm[128], 1);
    }

    // ---- init: tf32-round w_hh -> g_w; tf32-round h0 -> g_h buf0 ----
    {
        const float4* src = (const float4*)w_hh;
        float4* dst = (float4*)g_w;
        int base = cid * ((NG * HH / 4) / NCTA);
        for (int i = tid; i < (NG * HH / 4) / NCTA; i += NTHR) {
            float4 v = src[base + i];
            v.x = tf32r(v.x); v.y = tf32r(v.y); v.z = tf32r(v.z); v.w = tf32r(v.w);
            dst[base + i] = v;
        }
        const float4* hs = (const float4*)h0;
        float4* hd = (float4*)g_h;
        int hb = cid * ((BB * HH / 4) / NCTA);
        for (int i = tid; i < (BB * HH / 4) / NCTA; i += NTHR) {
            float4 v = hs[hb + i];
            v.x = tf32r(v.x); v.y = tf32r(v.y); v.z = tf32r(v.z); v.w = tf32r(v.w);
            hd[hb + i] = v;
        }
    }

    // ---- c state in registers: creg[rh*2+e], rows warp_m*16+rh*8+lg, units warp_n*8+2lt+e ----
    float creg[4];
    {
        const int u0 = unit0 + warp_n * 8 + (lt << 1);
#pragma unroll
        for (int rh = 0; rh < 2; rh++) {
            int r = warp_m * 16 + rh * 8 + lg;
            const float2 cv = *(const float2*)(c0 + (size_t)(b0 + r) * HH + u0);
            creg[rh * 2 + 0] = cv.x;
            creg[rh * 2 + 1] = cv.y;
        }
    }
    grid_sync();
    const int tok_is_32 = toksm[128];

    // ---- per-thread cp.async address precompute ----
    int a_src[4];  unsigned a_dst[4];
    int w_src[2];  unsigned w_dst[2];
#pragma unroll
    for (int i = 0; i < 4; i++) {
        int id = tid + NTHR * i;
        int r = id >> 4, q = id & 15;
        a_src[i] = r * HH + q * 4;
        a_dst[i] = (unsigned)((r * AS_STRIDE + q * 4) * 4);
    }
#pragma unroll
    for (int i = 0; i < 2; i++) {
        int id = tid + NTHR * i;
        int r = id >> 4, q = id & 15;
        w_src[i] = colIdx(r, unit0) * HH + q * 4;
        w_dst[i] = (unsigned)(((BT * AS_STRIDE) + r * AS_STRIDE + q * 4) * 4);
    }
    const unsigned bufb[3] = { sbase + OFF_B0 * 4, sbase + OFF_B1 * 4, sbase + OFF_B2 * 4 };

    // ---- per-lane ldmatrix offsets (bytes within a stage) ----
    unsigned a_lm, b_lm[2];
    {
        int row = warp_m * 16 + (lane & 7) + (((lane >> 3) & 1) << 3);
        int col = (lane >> 4) << 2;
        a_lm = (unsigned)((row * AS_STRIDE + col) * 4);
    }
#pragma unroll
    for (int p = 0; p < 2; p++) {
        int row = warp_n * 32 + p * 16 + (lane & 7) + ((lane >> 4) << 3);
        int col = ((lane >> 3) & 1) << 2;
        b_lm[p] = (unsigned)(((BT * AS_STRIDE) + row * AS_STRIDE + col) * 4);
    }

    // ---- P table: P[v][j] = emb[v] . w_ih[col(j)] + b_ih + b_hh ----
    {
        float* As = sm + OFF_B0;
        float* Ws = As + BT * AS_STRIDE;
        float acc[4][4];
#pragma unroll
        for (int nb = 0; nb < 4; nb++)
#pragma unroll
            for (int e = 0; e < 4; e++) acc[nb][e] = 0.f;

        for (int kc = 0; kc < II; kc += KC) {
            __syncthreads();
            load_tiles_cvt(As, Ws, emb, II, w_ih, II, kc, unit0, tid);
            __syncthreads();
            mma_chunk(bufb[0], a_lm, b_lm, acc);
        }
        __syncthreads();
        {
            int r0 = warp_m * 16 + lg;
#pragma unroll
            for (int nb = 0; nb < 4; nb++) {
                int c0c = warp_n * 32 + nb * 8 + (lt << 1);
                int gc0 = colIdx(c0c, unit0), gc1 = colIdx(c0c + 1, unit0);
                float bias0 = b_ih[gc0] + b_hh[gc0];
                float bias1 = b_ih[gc1] + b_hh[gc1];
                Psm[r0 * PS + c0c]           = acc[nb][0] + bias0;
                Psm[r0 * PS + c0c + 1]       = acc[nb][1] + bias1;
                Psm[(r0 + 8) * PS + c0c]     = acc[nb][2] + bias0;
                Psm[(r0 + 8) * PS + c0c + 1] = acc[nb][3] + bias1;
            }
        }
        __syncthreads();
    }

    // ---- issue W chunk 0 for step 0 (uncommitted; commits with A0) ----
#pragma unroll
    for (int i = 0; i < 2; i++) cpa16(bufb[0] + w_dst[i], g_w + w_src[i]);

    // ---- recurrence: 3-stage pipeline, ldmatrix fragments, register epilogue ----
    for (int t = 0; t < TT; t++) {
        const float* Ag = g_h + (size_t)(t & 1) * (BB * HH) + (size_t)b0 * HH;
        float* Hout = g_h + (size_t)((t + 1) & 1) * (BB * HH);

        if (tid < BT) {
            toksm[tid] = tok_is_32 ? inp32[t * BB + b0 + tid]
                                   : (int)inp64[(size_t)t * BB + b0 + tid];
        }

        float acc[4][4];
#pragma unroll
        for (int nb = 0; nb < 4; nb++)
#pragma unroll
            for (int e = 0; e < 4; e++) acc[nb][e] = 0.f;

        // A chunk 0 -> B0, commit group {W0, A0}; chunk 1 -> B1, commit
#pragma unroll
        for (int i = 0; i < 4; i++) cpa16(bufb[0] + a_dst[i], Ag + a_src[i]);
        CP_COMMIT();
#pragma unroll
        for (int i = 0; i < 4; i++) cpa16(bufb[1] + a_dst[i], Ag + a_src[i] + KC);
#pragma unroll
        for (int i = 0; i < 2; i++) cpa16(bufb[1] + w_dst[i], g_w + w_src[i] + KC);
        CP_COMMIT();

        // mainloop: wait(k) -> bar -> issue(k+2) -> mma(k)
        int cur = 0, nxt2 = 2;
#pragma unroll 1
        for (int kc = 0; kc < NKC; kc++) {
            if (kc < NKC - 1) cp_wait<1>(); else cp_wait<0>();
            __syncthreads();
            if (kc + 2 < NKC) {
                const int koff = (kc + 2) * KC;
                const unsigned nb_ = bufb[nxt2];
#pragma unroll
                for (int i = 0; i < 4; i++) cpa16(nb_ + a_dst[i], Ag + a_src[i] + koff);
#pragma unroll
                for (int i = 0; i < 2; i++) cpa16(nb_ + w_dst[i], g_w + w_src[i] + koff);
                CP_COMMIT();
            }
            mma_chunk(bufb[cur], a_lm, b_lm, acc);
            cur = (cur == 2) ? 0 : cur + 1;
            nxt2 = (nxt2 == 2) ? 0 : nxt2 + 1;
        }
        __syncthreads();   // all warps done mma(15) before B0 reuse

        const bool last = (t == TT - 1);
        if (!last) {
#pragma unroll
            for (int i = 0; i < 2; i++) cpa16(bufb[0] + w_dst[i], g_w + w_src[i]);
        }

        // ---- register epilogue ----
        {
            const int u0 = unit0 + warp_n * 8 + (lt << 1);
            const int pc = warp_n * 32 + (lt << 1);
            int r0 = warp_m * 16 + lg;
            int v0 = toksm[r0], v1 = toksm[r0 + 8];
            float gv4[4][4];
#pragma unroll
            for (int g = 0; g < 4; g++) {
                const float* P0 = Psm + v0 * PS + pc + g * 8;
                const float* P1 = Psm + v1 * PS + pc + g * 8;
                gv4[g][0] = acc[g][0] + P0[0];
                gv4[g][1] = acc[g][1] + P0[1];
                gv4[g][2] = acc[g][2] + P1[0];
                gv4[g][3] = acc[g][3] + P1[1];
            }
#pragma unroll
            for (int rh = 0; rh < 2; rh++) {
                float hv[2];
#pragma unroll
                for (int e = 0; e < 2; e++) {
                    int ix = rh * 2 + e;
                    float iv = fsig(gv4[0][ix]);
                    float fv = fsig(gv4[1][ix]);
                    float gg = ftanh(gv4[2][ix]);
                    float ov = fsig(gv4[3][ix]);
                    float cn = fv * creg[ix] + iv * gg;
                    float hn = ov * ftanh(cn);
                    creg[ix] = cn;
                    hv[e] = last ? hn : tf32r(hn);
                }
                int r = r0 + rh * 8;
                *(float2*)(Hout + (size_t)(b0 + r) * HH + u0) = make_float2(hv[0], hv[1]);
            }
        }
        grid_sync();
    }

    // ---- output head: h_last (fp32) in buffer 0 ----
    if (tid < 128) {
        int id = cid * 128 + tid;
        int b = id >> 6, o = id & 63;
        const float4* hr = (const float4*)(g_h + (size_t)b * HH);
        const float4* wr = (const float4*)(w_out + (size_t)o * HH);
        float s = 0.f;
#pragma unroll 8
        for (int k = 0; k < HH / 4; k++) {
            float4 a = __ldcg(hr + k);
            float4 w = wr[k];
            s += a.x * w.x + a.y * w.y + a.z * w.z + a.w * w.w;
        }
        out[id] = s + b_out[o];
    }
}

extern "C" void kernel_launch(void* const* d_in, const int* in_sizes, int n_in,
                              void* d_out, int out_size) {
    (void)in_sizes; (void)n_in; (void)out_size;
    const size_t smem_bytes = (size_t)SMEM_FLOATS * sizeof(float);
    cudaFuncSetAttribute(lstm_persistent_kernel,
                         cudaFuncAttributeMaxDynamicSharedMemorySize, (int)smem_bytes);
    lstm_persistent_kernel<<<NCTA, NTHR, smem_bytes>>>(
        (const void*)d_in[0],
        (const float*)d_in[1],
        (const float*)d_in[2],
        (const float*)d_in[3],
        (const float*)d_in[4],
        (const float*)d_in[5],
        (const float*)d_in[6],
        (const float*)d_in[7],
        (const float*)d_in[8],
        (const float*)d_in[9],
        (float*)d_out);
}

// round 14
// speedup vs baseline: 1.0264x; 1.0264x over previous
#include <cuda_runtime.h>
#include <cstdint>

// Problem dims
#define TT 128
#define BB 256
#define II 512
#define HH 1024
#define VV 128
#define OO 64
#define NG 4096   // 4*H

// Decomposition: 256 CTAs = 4 batch-blocks x 64 unit-blocks, 2 CTAs per SM
#define NCTA 256
#define BT 64           // batch rows per CTA (M)
#define UT 16           // hidden units per CTA
#define CT 64           // gate cols per CTA (N)
#define KC 64           // K chunk
#define NKC (HH/KC)     // 16
#define NTHR 256        // 8 warps: 4x2 grid, 16x32 tile per warp

#define AS_STRIDE 68
#define STAGE_FLOATS ((BT + CT) * AS_STRIDE)   // 128*68 = 8704

#define PS 65           // P table row stride

// smem float offsets (2 stages; total 25864 floats = 103456 B -> 2 CTAs/SM)
#define OFF_P   0                         // 128*65 = 8320
#define OFF_TOK 8320                      // 136 ints
#define OFF_B0  8456
#define OFF_B1  (OFF_B0 + STAGE_FLOATS)   // 17160
#define SMEM_FLOATS (OFF_B1 + STAGE_FLOATS)   // 25864

// ---- static scratch ----
__device__ float g_h[2*BB*HH];        // ping-pong hidden state (tf32; fp32 last step)
__device__ float g_w[NG*HH];          // tf32-pre-rounded w_hh
__device__ unsigned g_cnt;
__device__ unsigned g_rel;

__device__ __forceinline__ float tf32r(float x) {
    unsigned v; asm("cvt.rna.tf32.f32 %0, %1;" : "=r"(v) : "f"(x));
    return __uint_as_float(v);
}
__device__ __forceinline__ unsigned ld_acq(const unsigned* p) {
    unsigned v; asm volatile("ld.acquire.gpu.u32 %0, [%1];" : "=r"(v) : "l"(p) : "memory");
    return v;
}
__device__ __forceinline__ void grid_sync() {
    __syncthreads();
    if (threadIdx.x == 0) {
        unsigned r0 = ld_acq(&g_rel);
        __threadfence();
        unsigned old = atomicAdd(&g_cnt, 1u);
        if (old == (unsigned)(NCTA - 1)) {
            g_cnt = 0; __threadfence(); atomicAdd(&g_rel, 1u);
        } else {
            while (ld_acq(&g_rel) == r0) { }
        }
    }
    __syncthreads();
}

// col j -> gate=(j>>3)&3, unit=(j>>5)*8+(j&7): all 4 gates of a cell in one thread.
__device__ __forceinline__ int colIdx(int j, int unit0) {
    return (((j >> 3) & 3) << 10) + unit0 + ((j >> 5) << 3) + (j & 7);
}

__device__ __forceinline__ void mma8(float d[4], const unsigned a[4],
                                     unsigned b0, unsigned b1) {
    asm volatile(
        "mma.sync.aligned.m16n8k8.row.col.f32.tf32.tf32.f32 "
        "{%0,%1,%2,%3}, {%4,%5,%6,%7}, {%8,%9}, {%0,%1,%2,%3};\n"
        : "+f"(d[0]), "+f"(d[1]), "+f"(d[2]), "+f"(d[3])
        : "r"(a[0]), "r"(a[1]), "r"(a[2]), "r"(a[3]), "r"(b0), "r"(b1));
}
__device__ __forceinline__ void ldsm4(unsigned addr, unsigned& r0, unsigned& r1,
                                      unsigned& r2, unsigned& r3) {
    asm volatile("ldmatrix.sync.aligned.m8n8.x4.shared.b16 {%0,%1,%2,%3}, [%4];"
                 : "=r"(r0), "=r"(r1), "=r"(r2), "=r"(r3) : "r"(addr));
}
__device__ __forceinline__ void cpa16(unsigned dst, const float* src) {
    asm volatile("cp.async.cg.shared.global [%0], [%1], 16;" :: "r"(dst), "l"(src));
}
#define CP_COMMIT() asm volatile("cp.async.commit_group;" ::: "memory")
template<int N> __device__ __forceinline__ void cp_wait() {
    asm volatile("cp.async.wait_group %0;" :: "n"(N) : "memory");
}

// fast pointwise ops
__device__ __forceinline__ float fsig(float x) {
    return __fdividef(1.0f, 1.0f + __expf(-x));
}
__device__ __forceinline__ float ftanh(float x) {
    return 1.0f - 2.0f * __fdividef(1.0f, __expf(2.0f * x) + 1.0f);
}

// Synchronous tile load with tf32 rounding (P-table phase only). A: 64 rows.
__device__ __forceinline__ void load_tiles_cvt(
    float* As, float* Ws,
    const float* __restrict__ A, int lda,
    const float* __restrict__ W, int ldw,
    int kc, int unit0, int tid)
{
#pragma unroll
    for (int i = 0; i < 4; i++) {               // A: 1024 float4 / 256 thr
        int id = tid + NTHR * i;
        int r = id >> 4, q = id & 15;
        float4 v = __ldcg((const float4*)(A + (size_t)r * lda + kc + q * 4));
        v.x = tf32r(v.x); v.y = tf32r(v.y); v.z = tf32r(v.z); v.w = tf32r(v.w);
        *(float4*)(As + r * AS_STRIDE + q * 4) = v;
    }
#pragma unroll
    for (int i = 0; i < 4; i++) {               // W: 1024 float4 / 256 thr
        int id = tid + NTHR * i;
        int r = id >> 4, q = id & 15;
        float4 v = __ldcg((const float4*)(W + (size_t)colIdx(r, unit0) * ldw + kc + q * 4));
        v.x = tf32r(v.x); v.y = tf32r(v.y); v.z = tf32r(v.z); v.w = tf32r(v.w);
        *(float4*)(Ws + r * AS_STRIDE + q * 4) = v;
    }
}

// ldmatrix-based chunk MMA for 4x2 grid: 1 A x4 fragment (16 rows), 2 B x4 fragments.
__device__ __forceinline__ void mma_chunk(
    unsigned stg, unsigned a_lm, const unsigned b_lm[2],
    float acc[4][4])
{
#pragma unroll
    for (int kk = 0; kk < KC; kk += 8) {
        unsigned a[4], b[2][4];
        ldsm4(stg + a_lm + kk * 4, a[0], a[1], a[2], a[3]);
        ldsm4(stg + b_lm[0] + kk * 4, b[0][0], b[0][1], b[0][2], b[0][3]);
        ldsm4(stg + b_lm[1] + kk * 4, b[1][0], b[1][1], b[1][2], b[1][3]);
        mma8(acc[0], a, b[0][0], b[0][1]);
        mma8(acc[1], a, b[0][2], b[0][3]);
        mma8(acc[2], a, b[1][0], b[1][1]);
        mma8(acc[3], a, b[1][2], b[1][3]);
    }
}

__global__ void __launch_bounds__(NTHR, 2)
lstm_persistent_kernel(
    const void* __restrict__ inp_raw,
    const float* __restrict__ h0,
    const float* __restrict__ c0,
    const float* __restrict__ emb,
    const float* __restrict__ w_ih,
    const float* __restrict__ w_hh,
    const float* __restrict__ b_ih,
    const float* __restrict__ b_hh,
    const float* __restrict__ w_out,
    const float* __restrict__ b_out,
    float* __restrict__ out)
{
    extern __shared__ float sm[];
    float* Psm   = sm + OFF_P;
    int*   toksm = (int*)(sm + OFF_TOK);

    const int tid  = threadIdx.x;
    const int lane = tid & 31, wid = tid >> 5;
    const int warp_m = wid >> 1, warp_n = wid & 1;  // 4x2
    const int cid = blockIdx.x;
    const int bi = cid >> 6, hi = cid & 63;         // 4 batch x 64 unit blocks
    const int b0 = bi * BT;
    const int unit0 = hi * UT;
    const int lg = lane >> 2, lt = lane & 3;

    const unsigned sbase = (unsigned)__cvta_generic_to_shared(sm);
    const int* inp32 = (const int*)inp_raw;
    const long long* inp64 = (const long long*)inp_raw;

    // ---- token dtype detection ----
    if (tid == 0) toksm[128] = 0;
    __syncthreads();
    {
        int f = 0;
        for (int i = tid; i < 128; i += NTHR)
            if (inp32[2 * i + 1] != 0) f = 1;
        if (f) atomicOr(&toksm[128], 1);
    }

    // ---- init: tf32-round w_hh -> g_w; tf32-round h0 -> g_h buf0 ----
    {
        const float4* src = (const float4*)w_hh;
        float4* dst = (float4*)g_w;
        int base = cid * ((NG * HH / 4) / NCTA);            // 4096 float4 per CTA
        for (int i = tid; i < (NG * HH / 4) / NCTA; i += NTHR) {
            float4 v = src[base + i];
            v.x = tf32r(v.x); v.y = tf32r(v.y); v.z = tf32r(v.z); v.w = tf32r(v.w);
            dst[base + i] = v;
        }
        const float4* hs = (const float4*)h0;
        float4* hd = (float4*)g_h;
        int hb = cid * ((BB * HH / 4) / NCTA);              // 256 float4 per CTA
        for (int i = tid; i < (BB * HH / 4) / NCTA; i += NTHR) {
            float4 v = hs[hb + i];
            v.x = tf32r(v.x); v.y = tf32r(v.y); v.z = tf32r(v.z); v.w = tf32r(v.w);
            hd[hb + i] = v;
        }
    }

    // ---- c state in registers: creg[rh*2+e], rows warp_m*16+rh*8+lg, units warp_n*8+2lt+e ----
    float creg[4];
    {
        const int u0 = unit0 + warp_n * 8 + (lt << 1);
#pragma unroll
        for (int rh = 0; rh < 2; rh++) {
            int r = warp_m * 16 + rh * 8 + lg;
            const float2 cv = *(const float2*)(c0 + (size_t)(b0 + r) * HH + u0);
            creg[rh * 2 + 0] = cv.x;
            creg[rh * 2 + 1] = cv.y;
        }
    }
    grid_sync();
    const int tok_is_32 = toksm[128];

    // ---- per-thread cp.async address precompute (A: 64 rows, W: 64 rows) ----
    int a_src[4];  unsigned a_dst[4];
    int w_src[4];  unsigned w_dst[4];
#pragma unroll
    for (int i = 0; i < 4; i++) {
        int id = tid + NTHR * i;
        int r = id >> 4, q = id & 15;
        a_src[i] = r * HH + q * 4;
        a_dst[i] = (unsigned)((r * AS_STRIDE + q * 4) * 4);
        w_src[i] = colIdx(r, unit0) * HH + q * 4;
        w_dst[i] = (unsigned)(((BT * AS_STRIDE) + r * AS_STRIDE + q * 4) * 4);
    }
    const unsigned bufb[2] = { sbase + OFF_B0 * 4, sbase + OFF_B1 * 4 };

    // ---- per-lane ldmatrix offsets (bytes within a stage) ----
    unsigned a_lm, b_lm[2];
    {
        int row = warp_m * 16 + (lane & 7) + (((lane >> 3) & 1) << 3);
        int col = (lane >> 4) << 2;
        a_lm = (unsigned)((row * AS_STRIDE + col) * 4);
    }
#pragma unroll
    for (int p = 0; p < 2; p++) {
        int row = warp_n * 32 + p * 16 + (lane & 7) + ((lane >> 4) << 3);
        int col = ((lane >> 3) & 1) << 2;
        b_lm[p] = (unsigned)(((BT * AS_STRIDE) + row * AS_STRIDE + col) * 4);
    }

    // ---- P table: P[v][j] = emb[v] . w_ih[col(j)] + biases; 2 vocab halves of 64 rows ----
    for (int vb = 0; vb < 2; vb++) {
        float* As = sm + OFF_B0;
        float* Ws = As + BT * AS_STRIDE;
        float acc[4][4];
#pragma unroll
        for (int nb = 0; nb < 4; nb++)
#pragma unroll
            for (int e = 0; e < 4; e++) acc[nb][e] = 0.f;

        const float* Aemb = emb + (size_t)vb * 64 * II;
        for (int kc = 0; kc < II; kc += KC) {
            __syncthreads();
            load_tiles_cvt(As, Ws, Aemb, II, w_ih, II, kc, unit0, tid);
            __syncthreads();
            mma_chunk(bufb[0], a_lm, b_lm, acc);
        }
        __syncthreads();
        {
            int r0 = vb * 64 + warp_m * 16 + lg;
#pragma unroll
            for (int nb = 0; nb < 4; nb++) {
                int c0c = warp_n * 32 + nb * 8 + (lt << 1);
                int gc0 = colIdx(c0c, unit0), gc1 = colIdx(c0c + 1, unit0);
                float bias0 = b_ih[gc0] + b_hh[gc0];
                float bias1 = b_ih[gc1] + b_hh[gc1];
                Psm[r0 * PS + c0c]           = acc[nb][0] + bias0;
                Psm[r0 * PS + c0c + 1]       = acc[nb][1] + bias1;
                Psm[(r0 + 8) * PS + c0c]     = acc[nb][2] + bias0;
                Psm[(r0 + 8) * PS + c0c + 1] = acc[nb][3] + bias1;
            }
        }
        __syncthreads();
    }

    // ---- issue W chunk 0 for step 0 (uncommitted; commits with A0) ----
#pragma unroll
    for (int i = 0; i < 4; i++) cpa16(bufb[0] + w_dst[i], g_w + w_src[i]);

    // ---- recurrence: 2-stage pipeline, safe order wait -> bar -> issue -> mma ----
    for (int t = 0; t < TT; t++) {
        const float* Ag = g_h + (size_t)(t & 1) * (BB * HH) + (size_t)b0 * HH;
        float* Hout = g_h + (size_t)((t + 1) & 1) * (BB * HH);

        if (tid < BT) {
            toksm[tid] = tok_is_32 ? inp32[t * BB + b0 + tid]
                                   : (int)inp64[(size_t)t * BB + b0 + tid];
        }

        float acc[4][4];
#pragma unroll
        for (int nb = 0; nb < 4; nb++)
#pragma unroll
            for (int e = 0; e < 4; e++) acc[nb][e] = 0.f;

        // A chunk 0 -> B0, commit group {W0, A0}
#pragma unroll
        for (int i = 0; i < 4; i++) cpa16(bufb[0] + a_dst[i], Ag + a_src[i]);
        CP_COMMIT();

        // mainloop: wait(kc) -> bar -> issue(kc+1) -> mma(kc)
#pragma unroll 1
        for (int kc = 0; kc < NKC; kc++) {
            const int cur = kc & 1;
            cp_wait<0>();
            __syncthreads();
            if (kc + 1 < NKC) {
                const int koff = (kc + 1) * KC;
                const unsigned nb_ = bufb[1 - cur];
#pragma unroll
                for (int i = 0; i < 4; i++) cpa16(nb_ + a_dst[i], Ag + a_src[i] + koff);
#pragma unroll
                for (int i = 0; i < 4; i++) cpa16(nb_ + w_dst[i], g_w + w_src[i] + koff);
                CP_COMMIT();
            }
            mma_chunk(bufb[cur], a_lm, b_lm, acc);
        }

        // issue next step's W0 into B0 (uncommitted). B0's last reader = mma(14),
        // which precedes the kc=15 barrier in every warp.
        const bool last = (t == TT - 1);
        if (!last) {
#pragma unroll
            for (int i = 0; i < 4; i++) cpa16(bufb[0] + w_dst[i], g_w + w_src[i]);
        }

        // ---- register epilogue ----
        {
            const int u0 = unit0 + warp_n * 8 + (lt << 1);
            const int pc = warp_n * 32 + (lt << 1);
            int r0 = warp_m * 16 + lg;
            int v0 = toksm[r0], v1 = toksm[r0 + 8];
            float gv4[4][4];
#pragma unroll
            for (int g = 0; g < 4; g++) {
                const float* P0 = Psm + v0 * PS + pc + g * 8;
                const float* P1 = Psm + v1 * PS + pc + g * 8;
                gv4[g][0] = acc[g][0] + P0[0];
                gv4[g][1] = acc[g][1] + P0[1];
                gv4[g][2] = acc[g][2] + P1[0];
                gv4[g][3] = acc[g][3] + P1[1];
            }
#pragma unroll
            for (int rh = 0; rh < 2; rh++) {
                float hv[2];
#pragma unroll
                for (int e = 0; e < 2; e++) {
                    int ix = rh * 2 + e;
                    float iv = fsig(gv4[0][ix]);
                    float fv = fsig(gv4[1][ix]);
                    float gg = ftanh(gv4[2][ix]);
                    float ov = fsig(gv4[3][ix]);
                    float cn = fv * creg[ix] + iv * gg;
                    float hn = ov * ftanh(cn);
                    creg[ix] = cn;
                    hv[e] = last ? hn : tf32r(hn);
                }
                int r = r0 + rh * 8;
                *(float2*)(Hout + (size_t)(b0 + r) * HH + u0) = make_float2(hv[0], hv[1]);
            }
        }
        grid_sync();
    }

    // ---- output head: h_last (fp32) in buffer 0 ----
    if (tid < 64) {
        int id = cid * 64 + tid;              // 256 CTAs x 64 = 16384 = 256*64
        int b = id >> 6, o = id & 63;
        const float4* hr = (const float4*)(g_h + (size_t)b * HH);
        const float4* wr = (const float4*)(w_out + (size_t)o * HH);
        float s = 0.f;
#pragma unroll 8
        for (int k = 0; k < HH / 4; k++) {
            float4 a = __ldcg(hr + k);
            float4 w = wr[k];
            s += a.x * w.x + a.y * w.y + a.z * w.z + a.w * w.w;
        }
        out[id] = s + b_out[o];
    }
}

extern "C" void kernel_launch(void* const* d_in, const int* in_sizes, int n_in,
                              void* d_out, int out_size) {
    (void)in_sizes; (void)n_in; (void)out_size;
    const size_t smem_bytes = (size_t)SMEM_FLOATS * sizeof(float);
    cudaFuncSetAttribute(lstm_persistent_kernel,
                         cudaFuncAttributeMaxDynamicSharedMemorySize, (int)smem_bytes);
    lstm_persistent_kernel<<<NCTA, NTHR, smem_bytes>>>(
        (const void*)d_in[0],
        (const float*)d_in[1],
        (const float*)d_in[2],
        (const float*)d_in[3],
        (const float*)d_in[4],
        (const float*)d_in[5],
        (const float*)d_in[6],
        (const float*)d_in[7],
        (const float*)d_in[8],
        (const float*)d_in[9],
        (float*)d_out);
}

// round 15
// speedup vs baseline: 1.2107x; 1.1796x over previous
#include <cuda_runtime.h>
#include <cstdint>

// Problem dims
#define TT 128
#define BB 256
#define II 512
#define HH 1024
#define VV 128
#define OO 64
#define NG 4096   // 4*H

// Decomposition (champion shape)
#define NCTA 128        // 2 batch-blocks x 64 unit-blocks
#define BT 128          // batch rows per CTA (M)
#define UT 16           // hidden units per CTA
#define CT 64           // gate cols per CTA (N)
#define KC 64           // K chunk
#define NKC (HH/KC)     // 16
#define NTHR 256        // 8 warps: 4x2 warp grid, 32x32 tile per warp

#define AS_STRIDE 68
#define STAGE_FLOATS ((BT + CT) * AS_STRIDE)   // 13056

// smem float offsets: tokens + 4 pipeline stages (P table now in global scratch)
#define OFF_TOK 0                         // 136 ints
#define OFF_B0  136
#define SMEM_FLOATS (OFF_B0 + 4*STAGE_FLOATS)   // 52360 floats = 209440 B

// ---- static scratch ----
__device__ float g_h[2*BB*HH];        // ping-pong hidden state (tf32; fp32 last step)
__device__ float g_w[NG*HH];          // tf32-pre-rounded w_hh
__device__ float g_p[NCTA*VV*CT];     // 4 MB P table: per-CTA slice [128 vocab x 64 cols]
__device__ unsigned g_cnt;
__device__ unsigned g_rel;

__device__ __forceinline__ float tf32r(float x) {
    unsigned v; asm("cvt.rna.tf32.f32 %0, %1;" : "=r"(v) : "f"(x));
    return __uint_as_float(v);
}
__device__ __forceinline__ unsigned ld_acq(const unsigned* p) {
    unsigned v; asm volatile("ld.acquire.gpu.u32 %0, [%1];" : "=r"(v) : "l"(p) : "memory");
    return v;
}
__device__ __forceinline__ void grid_sync() {
    __syncthreads();
    if (threadIdx.x == 0) {
        unsigned r0 = ld_acq(&g_rel);
        __threadfence();
        unsigned old = atomicAdd(&g_cnt, 1u);
        if (old == (unsigned)(NCTA - 1)) {
            g_cnt = 0; __threadfence(); atomicAdd(&g_rel, 1u);
        } else {
            while (ld_acq(&g_rel) == r0) { }
        }
    }
    __syncthreads();
}

// col j -> gate=(j>>3)&3, unit=(j>>5)*8+(j&7): all 4 gates of a cell in one thread.
__device__ __forceinline__ int colIdx(int j, int unit0) {
    return (((j >> 3) & 3) << 10) + unit0 + ((j >> 5) << 3) + (j & 7);
}

__device__ __forceinline__ void mma8(float d[4], const unsigned a[4],
                                     unsigned b0, unsigned b1) {
    asm volatile(
        "mma.sync.aligned.m16n8k8.row.col.f32.tf32.tf32.f32 "
        "{%0,%1,%2,%3}, {%4,%5,%6,%7}, {%8,%9}, {%0,%1,%2,%3};\n"
        : "+f"(d[0]), "+f"(d[1]), "+f"(d[2]), "+f"(d[3])
        : "r"(a[0]), "r"(a[1]), "r"(a[2]), "r"(a[3]), "r"(b0), "r"(b1));
}
__device__ __forceinline__ void ldsm4(unsigned addr, unsigned& r0, unsigned& r1,
                                      unsigned& r2, unsigned& r3) {
    asm volatile("ldmatrix.sync.aligned.m8n8.x4.shared.b16 {%0,%1,%2,%3}, [%4];"
                 : "=r"(r0), "=r"(r1), "=r"(r2), "=r"(r3) : "r"(addr));
}
__device__ __forceinline__ void cpa16(unsigned dst, const float* src) {
    asm volatile("cp.async.cg.shared.global [%0], [%1], 16;" :: "r"(dst), "l"(src));
}
#define CP_COMMIT() asm volatile("cp.async.commit_group;" ::: "memory")
template<int N> __device__ __forceinline__ void cp_wait() {
    asm volatile("cp.async.wait_group %0;" :: "n"(N) : "memory");
}

// fast pointwise ops
__device__ __forceinline__ float fsig(float x) {
    return __fdividef(1.0f, 1.0f + __expf(-x));
}
__device__ __forceinline__ float ftanh(float x) {
    return 1.0f - 2.0f * __fdividef(1.0f, __expf(2.0f * x) + 1.0f);
}

// Synchronous tile load with tf32 rounding (P-table phase only).
__device__ __forceinline__ void load_tiles_cvt(
    float* As, float* Ws,
    const float* __restrict__ A, int lda,
    const float* __restrict__ W, int ldw,
    int kc, int unit0, int tid)
{
#pragma unroll
    for (int i = 0; i < 8; i++) {
        int id = tid + NTHR * i;
        int r = id >> 4, q = id & 15;
        float4 v = __ldcg((const float4*)(A + (size_t)r * lda + kc + q * 4));
        v.x = tf32r(v.x); v.y = tf32r(v.y); v.z = tf32r(v.z); v.w = tf32r(v.w);
        *(float4*)(As + r * AS_STRIDE + q * 4) = v;
    }
#pragma unroll
    for (int i = 0; i < 4; i++) {
        int id = tid + NTHR * i;
        int r = id >> 4, q = id & 15;
        float4 v = __ldcg((const float4*)(W + (size_t)colIdx(r, unit0) * ldw + kc + q * 4));
        v.x = tf32r(v.x); v.y = tf32r(v.y); v.z = tf32r(v.z); v.w = tf32r(v.w);
        *(float4*)(Ws + r * AS_STRIDE + q * 4) = v;
    }
}

// ldmatrix-based chunk MMA (champion shape): 2 A x4 fragments, 2 B x4 fragments.
__device__ __forceinline__ void mma_chunk(
    unsigned stg, const unsigned a_lm[2], const unsigned b_lm[2],
    float acc[2][4][4])
{
#pragma unroll
    for (int kk = 0; kk < KC; kk += 8) {
        unsigned a[2][4], b[2][4];
        ldsm4(stg + a_lm[0] + kk * 4, a[0][0], a[0][1], a[0][2], a[0][3]);
        ldsm4(stg + a_lm[1] + kk * 4, a[1][0], a[1][1], a[1][2], a[1][3]);
        ldsm4(stg + b_lm[0] + kk * 4, b[0][0], b[0][1], b[0][2], b[0][3]);
        ldsm4(stg + b_lm[1] + kk * 4, b[1][0], b[1][1], b[1][2], b[1][3]);
#pragma unroll
        for (int mb = 0; mb < 2; mb++) {
            mma8(acc[mb][0], a[mb], b[0][0], b[0][1]);
            mma8(acc[mb][1], a[mb], b[0][2], b[0][3]);
            mma8(acc[mb][2], a[mb], b[1][0], b[1][1]);
            mma8(acc[mb][3], a[mb], b[1][2], b[1][3]);
        }
    }
}

__global__ void __launch_bounds__(NTHR, 1)
lstm_persistent_kernel(
    const void* __restrict__ inp_raw,
    const float* __restrict__ h0,
    const float* __restrict__ c0,
    const float* __restrict__ emb,
    const float* __restrict__ w_ih,
    const float* __restrict__ w_hh,
    const float* __restrict__ b_ih,
    const float* __restrict__ b_hh,
    const float* __restrict__ w_out,
    const float* __restrict__ b_out,
    float* __restrict__ out)
{
    extern __shared__ float sm[];
    int* toksm = (int*)(sm + OFF_TOK);

    const int tid  = threadIdx.x;
    const int lane = tid & 31, wid = tid >> 5;
    const int warp_m = wid >> 1, warp_n = wid & 1;  // 4x2
    const int cid = blockIdx.x;
    const int bi = cid >> 6, hi = cid & 63;
    const int b0 = bi * BT;
    const int unit0 = hi * UT;
    const int lg = lane >> 2, lt = lane & 3;

    const unsigned sbase = (unsigned)__cvta_generic_to_shared(sm);
    const int* inp32 = (const int*)inp_raw;
    const long long* inp64 = (const long long*)inp_raw;
    float* Pcta = g_p + (size_t)cid * (VV * CT);     // this CTA's P slice

    // ---- token dtype detection ----
    if (tid == 0) toksm[128] = 0;
    __syncthreads();
    {
        int f = 0;
        for (int i = tid; i < 128; i += NTHR)
            if (inp32[2 * i + 1] != 0) f = 1;
        if (f) atomicOr(&toksm[128], 1);
    }

    // ---- init: tf32-round w_hh -> g_w; tf32-round h0 -> g_h buf0 ----
    {
        const float4* src = (const float4*)w_hh;
        float4* dst = (float4*)g_w;
        int base = cid * ((NG * HH / 4) / NCTA);
        for (int i = tid; i < (NG * HH / 4) / NCTA; i += NTHR) {
            float4 v = src[base + i];
            v.x = tf32r(v.x); v.y = tf32r(v.y); v.z = tf32r(v.z); v.w = tf32r(v.w);
            dst[base + i] = v;
        }
        const float4* hs = (const float4*)h0;
        float4* hd = (float4*)g_h;
        int hb = cid * ((BB * HH / 4) / NCTA);
        for (int i = tid; i < (BB * HH / 4) / NCTA; i += NTHR) {
            float4 v = hs[hb + i];
            v.x = tf32r(v.x); v.y = tf32r(v.y); v.z = tf32r(v.z); v.w = tf32r(v.w);
            hd[hb + i] = v;
        }
    }

    // ---- c state in registers ----
    float creg[8];
    {
        const int u0 = unit0 + warp_n * 8 + (lt << 1);
#pragma unroll
        for (int mb = 0; mb < 2; mb++)
#pragma unroll
            for (int rh = 0; rh < 2; rh++) {
                int r = warp_m * 32 + mb * 16 + rh * 8 + lg;
                const float2 cv = *(const float2*)(c0 + (size_t)(b0 + r) * HH + u0);
                creg[mb * 4 + rh * 2 + 0] = cv.x;
                creg[mb * 4 + rh * 2 + 1] = cv.y;
            }
    }
    grid_sync();
    const int tok_is_32 = toksm[128];

    // ---- per-thread cp.async address precompute ----
    int a_src[8];  unsigned a_dst[8];
    int w_src[4];  unsigned w_dst[4];
#pragma unroll
    for (int i = 0; i < 8; i++) {
        int id = tid + NTHR * i;
        int r = id >> 4, q = id & 15;
        a_src[i] = r * HH + q * 4;
        a_dst[i] = (unsigned)((r * AS_STRIDE + q * 4) * 4);
    }
#pragma unroll
    for (int i = 0; i < 4; i++) {
        int id = tid + NTHR * i;
        int r = id >> 4, q = id & 15;
        w_src[i] = colIdx(r, unit0) * HH + q * 4;
        w_dst[i] = (unsigned)(((BT * AS_STRIDE) + r * AS_STRIDE + q * 4) * 4);
    }
    unsigned bufb[4];
#pragma unroll
    for (int s = 0; s < 4; s++) bufb[s] = sbase + (OFF_B0 + s * STAGE_FLOATS) * 4;

    // ---- per-lane ldmatrix offsets (bytes within a stage) ----
    unsigned a_lm[2], b_lm[2];
#pragma unroll
    for (int mb = 0; mb < 2; mb++) {
        int row = warp_m * 32 + mb * 16 + (lane & 7) + (((lane >> 3) & 1) << 3);
        int col = (lane >> 4) << 2;
        a_lm[mb] = (unsigned)((row * AS_STRIDE + col) * 4);
    }
#pragma unroll
    for (int p = 0; p < 2; p++) {
        int row = warp_n * 32 + p * 16 + (lane & 7) + ((lane >> 4) << 3);
        int col = ((lane >> 3) & 1) << 2;
        b_lm[p] = (unsigned)(((BT * AS_STRIDE) + row * AS_STRIDE + col) * 4);
    }

    // ---- P table: P[v][j] = emb[v] . w_ih[col(j)] + b_ih + b_hh  -> g_p (global) ----
    {
        float* As = sm + OFF_B0;
        float* Ws = As + BT * AS_STRIDE;
        float acc[2][4][4];
#pragma unroll
        for (int mb = 0; mb < 2; mb++)
#pragma unroll
            for (int nb = 0; nb < 4; nb++)
#pragma unroll
                for (int e = 0; e < 4; e++) acc[mb][nb][e] = 0.f;

        for (int kc = 0; kc < II; kc += KC) {
            __syncthreads();
            load_tiles_cvt(As, Ws, emb, II, w_ih, II, kc, unit0, tid);
            __syncthreads();
            mma_chunk(bufb[0], a_lm, b_lm, acc);
        }
        __syncthreads();
#pragma unroll
        for (int mb = 0; mb < 2; mb++) {
            int r0 = warp_m * 32 + mb * 16 + lg;
#pragma unroll
            for (int nb = 0; nb < 4; nb++) {
                int c0c = warp_n * 32 + nb * 8 + (lt << 1);
                int gc0 = colIdx(c0c, unit0), gc1 = colIdx(c0c + 1, unit0);
                float bias0 = b_ih[gc0] + b_hh[gc0];
                float bias1 = b_ih[gc1] + b_hh[gc1];
                Pcta[r0 * CT + c0c]           = acc[mb][nb][0] + bias0;
                Pcta[r0 * CT + c0c + 1]       = acc[mb][nb][1] + bias1;
                Pcta[(r0 + 8) * CT + c0c]     = acc[mb][nb][2] + bias0;
                Pcta[(r0 + 8) * CT + c0c + 1] = acc[mb][nb][3] + bias1;
            }
        }
        __threadfence();
        __syncthreads();
    }

    // ---- issue W chunk 0 for step 0 (uncommitted; commits with A0) ----
#pragma unroll
    for (int i = 0; i < 4; i++) cpa16(bufb[0] + w_dst[i], g_w + w_src[i]);

    // ---- recurrence: 4-stage pipeline, chunks processed in PAIRS (8 bars/step) ----
    for (int t = 0; t < TT; t++) {
        const float* Ag = g_h + (size_t)(t & 1) * (BB * HH) + (size_t)b0 * HH;
        float* Hout = g_h + (size_t)((t + 1) & 1) * (BB * HH);

        if (tid < BT) {
            toksm[tid] = tok_is_32 ? inp32[t * BB + b0 + tid]
                                   : (int)inp64[(size_t)t * BB + b0 + tid];
        }

        float acc[2][4][4];
#pragma unroll
        for (int mb = 0; mb < 2; mb++)
#pragma unroll
            for (int nb = 0; nb < 4; nb++)
#pragma unroll
                for (int e = 0; e < 4; e++) acc[mb][nb][e] = 0.f;

        // chunk 0 (A) -> stage0, commit {W0,A0}; chunk 1 (A+W) -> stage1, commit
#pragma unroll
        for (int i = 0; i < 8; i++) cpa16(bufb[0] + a_dst[i], Ag + a_src[i]);
        CP_COMMIT();
#pragma unroll
        for (int i = 0; i < 8; i++) cpa16(bufb[1] + a_dst[i], Ag + a_src[i] + KC);
#pragma unroll
        for (int i = 0; i < 4; i++) cpa16(bufb[1] + w_dst[i], g_w + w_src[i] + KC);
        CP_COMMIT();

        // pair loop: wait(2i,2i+1) -> bar -> issue(2i+2),(2i+3) -> mma(2i), mma(2i+1)
#pragma unroll 1
        for (int i = 0; i < NKC / 2; i++) {
            cp_wait<0>();
            __syncthreads();
            if (i < NKC / 2 - 1) {
                const int c2 = 2 * i + 2, c3 = 2 * i + 3;
                {
                    const int koff = c2 * KC;
                    const unsigned s_ = bufb[c2 & 3];
#pragma unroll
                    for (int j = 0; j < 8; j++) cpa16(s_ + a_dst[j], Ag + a_src[j] + koff);
#pragma unroll
                    for (int j = 0; j < 4; j++) cpa16(s_ + w_dst[j], g_w + w_src[j] + koff);
                    CP_COMMIT();
                }
                {
                    const int koff = c3 * KC;
                    const unsigned s_ = bufb[c3 & 3];
#pragma unroll
                    for (int j = 0; j < 8; j++) cpa16(s_ + a_dst[j], Ag + a_src[j] + koff);
#pragma unroll
                    for (int j = 0; j < 4; j++) cpa16(s_ + w_dst[j], g_w + w_src[j] + koff);
                    CP_COMMIT();
                }
            }
            mma_chunk(bufb[(2 * i) & 3], a_lm, b_lm, acc);
            mma_chunk(bufb[(2 * i + 1) & 3], a_lm, b_lm, acc);
        }

        // issue next step's W0 into stage0 (uncommitted). stage0's last reader was
        // mma(12) at pair-iter 6; every warp passed the iter-7 barrier after it.
        const bool last = (t == TT - 1);
        if (!last) {
#pragma unroll
            for (int i = 0; i < 4; i++) cpa16(bufb[0] + w_dst[i], g_w + w_src[i]);
        }

        // ---- register epilogue: gates = acc + P[token] (global LDG), LSTM cell ----
        {
            const int u0 = unit0 + warp_n * 8 + (lt << 1);
            const int pc = warp_n * 32 + (lt << 1);
#pragma unroll
            for (int mb = 0; mb < 2; mb++) {
                int r0 = warp_m * 32 + mb * 16 + lg;
                int v0 = toksm[r0], v1 = toksm[r0 + 8];
                float gv4[4][4];
#pragma unroll
                for (int g = 0; g < 4; g++) {
                    const float2 P0 = *(const float2*)(Pcta + v0 * CT + pc + g * 8);
                    const float2 P1 = *(const float2*)(Pcta + v1 * CT + pc + g * 8);
                    gv4[g][0] = acc[mb][g][0] + P0.x;
                    gv4[g][1] = acc[mb][g][1] + P0.y;
                    gv4[g][2] = acc[mb][g][2] + P1.x;
                    gv4[g][3] = acc[mb][g][3] + P1.y;
                }
#pragma unroll
                for (int rh = 0; rh < 2; rh++) {
                    float hv[2];
#pragma unroll
                    for (int e = 0; e < 2; e++) {
                        int ix = rh * 2 + e;
                        float iv = fsig(gv4[0][ix]);
                        float fv = fsig(gv4[1][ix]);
                        float gg = ftanh(gv4[2][ix]);
                        float ov = fsig(gv4[3][ix]);
                        float cn = fv * creg[mb * 4 + ix] + iv * gg;
                        float hn = ov * ftanh(cn);
                        creg[mb * 4 + ix] = cn;
                        hv[e] = last ? hn : tf32r(hn);
                    }
                    int r = r0 + rh * 8;
                    *(float2*)(Hout + (size_t)(b0 + r) * HH + u0) = make_float2(hv[0], hv[1]);
                }
            }
        }
        grid_sync();
    }

    // ---- output head: h_last (fp32) in buffer 0 ----
    if (tid < 128) {
        int id = cid * 128 + tid;
        int b = id >> 6, o = id & 63;
        const float4* hr = (const float4*)(g_h + (size_t)b * HH);
        const float4* wr = (const float4*)(w_out + (size_t)o * HH);
        float s = 0.f;
#pragma unroll 8
        for (int k = 0; k < HH / 4; k++) {
            float4 a = __ldcg(hr + k);
            float4 w = wr[k];
            s += a.x * w.x + a.y * w.y + a.z * w.z + a.w * w.w;
        }
        out[id] = s + b_out[o];
    }
}

extern "C" void kernel_launch(void* const* d_in, const int* in_sizes, int n_in,
                              void* d_out, int out_size) {
    (void)in_sizes; (void)n_in; (void)out_size;
    const size_t smem_bytes = (size_t)SMEM_FLOATS * sizeof(float);
    cudaFuncSetAttribute(lstm_persistent_kernel,
                         cudaFuncAttributeMaxDynamicSharedMemorySize, (int)smem_bytes);
    lstm_persistent_kernel<<<NCTA, NTHR, smem_bytes>>>(
        (const void*)d_in[0],
        (const float*)d_in[1],
        (const float*)d_in[2],
        (const float*)d_in[3],
        (const float*)d_in[4],
        (const float*)d_in[5],
        (const float*)d_in[6],
        (const float*)d_in[7],
        (const float*)d_in[8],
        (const float*)d_in[9],
        (float*)d_out);
}